// round 2
// baseline (speedup 1.0000x reference)
#include <cuda_runtime.h>
#include <cuda_bf16.h>

#define NE      100000
#define NN      10000
#define CUTF    5.5f

// Scratch accumulator: S[node][z(2)][rbf(8)][ang(20)] = 320 floats per node.
__device__ __align__(16) float g_S[NN * 320];

__global__ void zero_S_kernel() {
    int i = blockIdx.x * blockDim.x + threadIdx.x;
    const int n4 = NN * 320 / 4;
    if (i < n4) {
        reinterpret_cast<float4*>(g_S)[i] = make_float4(0.f, 0.f, 0.f, 0.f);
    }
}

__device__ __forceinline__ void red_add_v4(float* addr, float a, float b, float c, float d) {
    asm volatile("red.global.add.v4.f32 [%0], {%1,%2,%3,%4};"
                 :: "l"(addr), "f"(a), "f"(b), "f"(c), "f"(d) : "memory");
}

__global__ void edge_kernel(const int* __restrict__ ei,
                            const int* __restrict__ an,
                            const float* __restrict__ el,
                            const float* __restrict__ ev) {
    int e = blockIdx.x * blockDim.x + threadIdx.x;
    if (e >= NE) return;

    int src = ei[e];
    int dst = ei[NE + e];
    int z   = an[src];

    float r  = el[e];
    float vx = ev[3 * e + 0];
    float vy = ev[3 * e + 1];
    float vz = ev[3 * e + 2];
    float inv = rsqrtf(vx * vx + vy * vy + vz * vz);
    float x = vx * inv, y = vy * inv, zc = vz * inv;

    // Angular monomials (order per _lxlylz_list, MAX_L=3 -> 20 entries)
    float ang[20];
    ang[0]  = 1.0f;
    ang[1]  = x;        ang[2]  = y;        ang[3]  = zc;
    ang[4]  = x * x;    ang[5]  = x * y;    ang[6]  = x * zc;
    ang[7]  = y * y;    ang[8]  = y * zc;   ang[9]  = zc * zc;
    ang[10] = ang[4] * x;   // x^3
    ang[11] = ang[4] * y;   // x^2 y
    ang[12] = ang[4] * zc;  // x^2 z
    ang[13] = x * ang[7];   // x y^2
    ang[14] = ang[5] * zc;  // x y z
    ang[15] = x * ang[9];   // x z^2
    ang[16] = ang[7] * y;   // y^3
    ang[17] = ang[7] * zc;  // y^2 z
    ang[18] = y * ang[9];   // y z^2
    ang[19] = ang[9] * zc;  // z^3

    // Radial: sqrt(2/CUT) * sin(n*pi*r/CUT)/r * fc(u),  n = 1..8
    float u  = r * (1.0f / CUTF);
    float u2 = u * u;
    float u3 = u2 * u;
    float u6 = u3 * u3;
    float fc = 1.0f - 28.0f * u6 + 48.0f * u6 * u - 21.0f * u6 * u2;  // p=6
    fc = (u < 1.0f) ? fc : 0.0f;

    float s, c;
    sincosf(3.14159265358979323846f * u, &s, &c);     // theta = pi*r/CUT
    float scale = 0.60302268915552726f / r * fc;      // sqrt(2/5.5)/r * fc

    float* base = g_S + (size_t)dst * 320 + z * 160;

    // sin(n*theta) via Chebyshev recurrence: s_{n+1} = 2 cos(theta) s_n - s_{n-1}
    float sp = 0.0f, sn = s;
    float twoc = 2.0f * c;
#pragma unroll
    for (int n = 0; n < 8; n++) {
        float rad = scale * sn;
        float* p = base + n * 20;
        red_add_v4(p +  0, rad * ang[0],  rad * ang[1],  rad * ang[2],  rad * ang[3]);
        red_add_v4(p +  4, rad * ang[4],  rad * ang[5],  rad * ang[6],  rad * ang[7]);
        red_add_v4(p +  8, rad * ang[8],  rad * ang[9],  rad * ang[10], rad * ang[11]);
        red_add_v4(p + 12, rad * ang[12], rad * ang[13], rad * ang[14], rad * ang[15]);
        red_add_v4(p + 16, rad * ang[16], rad * ang[17], rad * ang[18], rad * ang[19]);
        float nx = twoc * sn - sp;
        sp = sn;
        sn = nx;
    }
}

// Level and multinomial prefactor per angular index
__constant__ int   c_lvl[20]  = {0, 1,1,1, 2,2,2,2,2,2, 3,3,3,3,3,3,3,3,3,3};
__constant__ float c_pref[20] = {1.f, 1.f,1.f,1.f,
                                 1.f,2.f,2.f,1.f,2.f,1.f,
                                 1.f,3.f,3.f,3.f,6.f,3.f,1.f,3.f,3.f,1.f};

__global__ void node_kernel(const int* __restrict__ an,
                            const float* __restrict__ W,   // [2,3]
                            float* __restrict__ out) {
    int t = blockIdx.x * blockDim.x + threadIdx.x;
    if (t >= NN * 8) return;
    int n = t >> 3;
    int r = t & 7;

    int z = an[n];
    float W00 = W[0], W01 = W[1], W02 = W[2];
    float W10 = W[3], W11 = W[4], W12 = W[5];

    const float* s0 = g_S + (size_t)n * 320 + r * 20;
    const float* s1 = s0 + 160;

    float D[4][3];
#pragma unroll
    for (int f = 0; f < 4; f++) { D[f][0] = 0.f; D[f][1] = 0.f; D[f][2] = 0.f; }

#pragma unroll
    for (int a = 0; a < 20; a++) {
        float v0 = s0[a];
        float v1 = s1[a];
        float C0 = v0 * W00 + v1 * W10;
        float C1 = v0 * W01 + v1 * W11;
        float C2 = v0 * W02 + v1 * W12;
        if (a == 0) {
            D[0][0] = C0; D[0][1] = C1; D[0][2] = C2;
        } else {
            int   l = c_lvl[a];
            float p = c_pref[a];
            D[l][0] += p * C0 * C0;
            D[l][1] += p * C1 * C1;
            D[l][2] += p * C2 * C2;
        }
    }

    float e0 = (z == 0) ? W00 : W10;
    float e1 = (z == 0) ? W01 : W11;
    float e2 = (z == 0) ? W02 : W12;
    float q0 = e0 * e0, q1 = e1 * e1, q2 = e2 * e2;

    float* o = out + (size_t)((n * 8 + r) * 4) * 9;
    // f = 0: B = C[r,0,i] * emb_j
    o[0] = D[0][0] * e0;  o[1] = D[0][0] * e1;  o[2] = D[0][0] * e2;
    o[3] = D[0][1] * e0;  o[4] = D[0][1] * e1;  o[5] = D[0][1] * e2;
    o[6] = D[0][2] * e0;  o[7] = D[0][2] * e1;  o[8] = D[0][2] * e2;
#pragma unroll
    for (int f = 1; f < 4; f++) {
        float* of = o + f * 9;
        of[0] = D[f][0] * q0;  of[1] = D[f][0] * q1;  of[2] = D[f][0] * q2;
        of[3] = D[f][1] * q0;  of[4] = D[f][1] * q1;  of[5] = D[f][1] * q2;
        of[6] = D[f][2] * q0;  of[7] = D[f][2] * q1;  of[8] = D[f][2] * q2;
    }
}

extern "C" void kernel_launch(void* const* d_in, const int* in_sizes, int n_in,
                              void* d_out, int out_size) {
    // inputs: positions(unused), atomic_numbers, edge_index, edge_lengths,
    //         edge_vectors, W_embed
    const int*   an = (const int*)d_in[1];
    const int*   ei = (const int*)d_in[2];
    const float* el = (const float*)d_in[3];
    const float* ev = (const float*)d_in[4];
    const float* W  = (const float*)d_in[5];
    float* out = (float*)d_out;

    {
        int n4 = NN * 320 / 4;
        zero_S_kernel<<<(n4 + 255) / 256, 256>>>();
    }
    edge_kernel<<<(NE + 255) / 256, 256>>>(ei, an, el, ev);
    node_kernel<<<(NN * 8 + 255) / 256, 256>>>(an, W, out);
}